// round 15
// baseline (speedup 1.0000x reference)
#include <cuda_runtime.h>
#include <cuda_bf16.h>
#include <cstdint>
#include <math.h>

#define D_MODEL 512
#define N_HEADS 8
#define D_HEAD 64
#define D_FF 2048
#define BATCH 4
#define SEQ 2048
#define M_TOTAL (BATCH * SEQ)   // 8192
#define BH (BATCH * N_HEADS)    // 32

typedef __nv_bfloat16 bf16;

// ---------------- scratch (no cudaMalloc allowed) ----------------
__device__ __align__(16) bf16  g_xh[M_TOTAL * D_MODEL];
__device__ __align__(16) bf16  g_xl[M_TOTAL * D_MODEL];
__device__ __align__(16) bf16  g_qh[M_TOTAL * D_MODEL];
__device__ __align__(16) bf16  g_ql[M_TOTAL * D_MODEL];
__device__ __align__(16) bf16  g_kh[M_TOTAL * D_MODEL];
__device__ __align__(16) bf16  g_kl[M_TOTAL * D_MODEL];
__device__ __align__(16) bf16  g_vh[M_TOTAL * D_MODEL];
__device__ __align__(16) bf16  g_vl[M_TOTAL * D_MODEL];
__device__ __align__(16) float g_attn[M_TOTAL * D_MODEL];
__device__ __align__(16) float g_x2[M_TOTAL * D_MODEL];
__device__ __align__(16) bf16  g_x2h[M_TOTAL * D_MODEL];
__device__ __align__(16) bf16  g_x2l[M_TOTAL * D_MODEL];
__device__ __align__(16) bf16  g_fh[M_TOTAL * D_FF];
__device__ __align__(16) bf16  g_fl[M_TOTAL * D_FF];
__device__ __align__(16) bf16  g_wqh[3 * D_MODEL * D_MODEL];
__device__ __align__(16) bf16  g_wql[3 * D_MODEL * D_MODEL];
__device__ __align__(16) bf16  g_w1h[D_FF * D_MODEL];
__device__ __align__(16) bf16  g_w1l[D_FF * D_MODEL];
__device__ __align__(16) bf16  g_w2h[D_MODEL * D_FF];
__device__ __align__(16) bf16  g_w2l[D_MODEL * D_FF];

// ---------------- helpers ----------------
__device__ __forceinline__ uint32_t smem_u32(const void* p) {
    uint32_t a;
    asm("{ .reg .u64 t; cvta.to.shared.u64 t, %1; cvt.u32.u64 %0, t; }" : "=r"(a) : "l"(p));
    return a;
}
__device__ __forceinline__ void cp16(uint32_t dst, const void* src) {
    asm volatile("cp.async.cg.shared.global [%0], [%1], 16;" :: "r"(dst), "l"(src));
}
#define CP_COMMIT() asm volatile("cp.async.commit_group;" ::: "memory")
#define CP_WAIT0()  asm volatile("cp.async.wait_group 0;" ::: "memory")
#define CP_WAIT1()  asm volatile("cp.async.wait_group 1;" ::: "memory")

__device__ __forceinline__ void ldsm4(uint32_t* r, uint32_t addr) {
    asm volatile("ldmatrix.sync.aligned.m8n8.x4.shared.b16 {%0,%1,%2,%3}, [%4];"
                 : "=r"(r[0]), "=r"(r[1]), "=r"(r[2]), "=r"(r[3]) : "r"(addr));
}
__device__ __forceinline__ void ldsm4t(uint32_t* r, uint32_t addr) {
    asm volatile("ldmatrix.sync.aligned.m8n8.x4.trans.shared.b16 {%0,%1,%2,%3}, [%4];"
                 : "=r"(r[0]), "=r"(r[1]), "=r"(r[2]), "=r"(r[3]) : "r"(addr));
}
__device__ __forceinline__ void mma16816(float* d, const uint32_t* a, uint32_t b0, uint32_t b1) {
    asm volatile(
        "mma.sync.aligned.m16n8k16.row.col.f32.bf16.bf16.f32 "
        "{%0,%1,%2,%3},{%4,%5,%6,%7},{%8,%9},{%0,%1,%2,%3};"
        : "+f"(d[0]), "+f"(d[1]), "+f"(d[2]), "+f"(d[3])
        : "r"(a[0]), "r"(a[1]), "r"(a[2]), "r"(a[3]), "r"(b0), "r"(b1));
}
__device__ __forceinline__ float sigmoid_fast(float xhalf) {
    float t;
    asm("tanh.approx.f32 %0, %1;" : "=f"(t) : "f"(xhalf));
    return fmaf(t, 0.5f, 0.5f);
}
__device__ __forceinline__ void split_pack(float v0, float v1, uint32_t& hp, uint32_t& lp) {
    bf16 h0 = __float2bfloat16(v0), h1 = __float2bfloat16(v1);
    __nv_bfloat162 h2; h2.x = h0; h2.y = h1;
    hp = *(uint32_t*)&h2;
    __nv_bfloat162 l2;
    l2.x = __float2bfloat16(v0 - __bfloat162float(h0));
    l2.y = __float2bfloat16(v1 - __bfloat162float(h1));
    lp = *(uint32_t*)&l2;
}

// ---------------- fused weight transpose + bf16 split (ALL 5 weights) ----------------
__global__ void transpose_split_all_kernel(
    const float* __restrict__ Wq, const float* __restrict__ Wk, const float* __restrict__ Wv,
    const float* __restrict__ W1, const float* __restrict__ W2,
    bf16* __restrict__ wqh, bf16* __restrict__ wql,
    bf16* __restrict__ w1h, bf16* __restrict__ w1l,
    bf16* __restrict__ w2h, bf16* __restrict__ w2l)
{
    int bid = blockIdx.x;
    const float* W; bf16 *oh, *ol; int K, N, n0, k0;
    if (bid < 768) {
        int idx = bid / 256, rem = bid % 256;
        W = (idx == 0) ? Wq : (idx == 1) ? Wk : Wv;
        oh = wqh + idx * D_MODEL * D_MODEL;
        ol = wql + idx * D_MODEL * D_MODEL;
        K = D_MODEL; N = D_MODEL;
        n0 = (rem & 15) * 32; k0 = (rem >> 4) * 32;
    } else if (bid < 1792) {
        int rem = bid - 768;
        W = W1; oh = w1h; ol = w1l;
        K = D_MODEL; N = D_FF;
        n0 = (rem & 63) * 32; k0 = (rem >> 6) * 32;
    } else {
        int rem = bid - 1792;
        W = W2; oh = w2h; ol = w2l;
        K = D_FF; N = D_MODEL;
        n0 = (rem & 15) * 32; k0 = (rem >> 4) * 32;
    }
    __shared__ float t[32][33];
    int x = threadIdx.x, y = threadIdx.y;
    #pragma unroll
    for (int i = 0; i < 4; i++)
        t[y + 8 * i][x] = W[(size_t)(k0 + y + 8 * i) * N + n0 + x];
    __syncthreads();
    #pragma unroll
    for (int i = 0; i < 4; i++) {
        float v = t[x][y + 8 * i];
        bf16 h = __float2bfloat16(v);
        bf16 l = __float2bfloat16(v - __bfloat162float(h));
        size_t o = (size_t)(n0 + y + 8 * i) * K + k0 + x;
        oh[o] = h; ol[o] = l;
    }
}

// ---------------- LayerNorm -> bf16 hi/lo ----------------
__global__ void ln_kernel(const float* __restrict__ x,
                          const float* __restrict__ g,
                          const float* __restrict__ beta,
                          bf16* __restrict__ oh, bf16* __restrict__ ol) {
    int row = blockIdx.x;
    int t = threadIdx.x;             // 128
    float4 v = ((const float4*)(x + (size_t)row * D_MODEL))[t];
    float s  = v.x + v.y + v.z + v.w;
    float s2 = v.x*v.x + v.y*v.y + v.z*v.z + v.w*v.w;
    #pragma unroll
    for (int o = 16; o; o >>= 1) {
        s  += __shfl_xor_sync(0xffffffffu, s,  o);
        s2 += __shfl_xor_sync(0xffffffffu, s2, o);
    }
    __shared__ float sh[8];
    int w = t >> 5, l = t & 31;
    if (l == 0) { sh[w] = s; sh[4 + w] = s2; }
    __syncthreads();
    s  = sh[0] + sh[1] + sh[2] + sh[3];
    s2 = sh[4] + sh[5] + sh[6] + sh[7];
    float mu  = s * (1.0f / D_MODEL);
    float var = s2 * (1.0f / D_MODEL) - mu * mu;
    float r = rsqrtf(var + 1e-5f);
    float4 gv = ((const float4*)g)[t];
    float4 bv = ((const float4*)beta)[t];
    float o4[4];
    o4[0] = (v.x - mu) * r * gv.x + bv.x;
    o4[1] = (v.y - mu) * r * gv.y + bv.y;
    o4[2] = (v.z - mu) * r * gv.z + bv.z;
    o4[3] = (v.w - mu) * r * gv.w + bv.w;
    size_t base = (size_t)row * D_MODEL + 4 * t;
    #pragma unroll
    for (int i = 0; i < 4; i++) {
        bf16 h = __float2bfloat16(o4[i]);
        oh[base + i] = h;
        ol[base + i] = __float2bfloat16(o4[i] - __bfloat162float(h));
    }
}

__global__ void addln_kernel(const float* __restrict__ x,
                             const float* __restrict__ attn,
                             const float* __restrict__ g,
                             const float* __restrict__ beta,
                             float* __restrict__ x2,
                             bf16* __restrict__ oh, bf16* __restrict__ ol) {
    int row = blockIdx.x;
    int t = threadIdx.x;
    float4 a = ((const float4*)(x + (size_t)row * D_MODEL))[t];
    float4 b = ((const float4*)(attn + (size_t)row * D_MODEL))[t];
    float4 v; v.x = a.x + b.x; v.y = a.y + b.y; v.z = a.z + b.z; v.w = a.w + b.w;
    ((float4*)(x2 + (size_t)row * D_MODEL))[t] = v;
    float s  = v.x + v.y + v.z + v.w;
    float s2 = v.x*v.x + v.y*v.y + v.z*v.z + v.w*v.w;
    #pragma unroll
    for (int o = 16; o; o >>= 1) {
        s  += __shfl_xor_sync(0xffffffffu, s,  o);
        s2 += __shfl_xor_sync(0xffffffffu, s2, o);
    }
    __shared__ float sh[8];
    int w = t >> 5, l = t & 31;
    if (l == 0) { sh[w] = s; sh[4 + w] = s2; }
    __syncthreads();
    s  = sh[0] + sh[1] + sh[2] + sh[3];
    s2 = sh[4] + sh[5] + sh[6] + sh[7];
    float mu  = s * (1.0f / D_MODEL);
    float var = s2 * (1.0f / D_MODEL) - mu * mu;
    float r = rsqrtf(var + 1e-5f);
    float4 gv = ((const float4*)g)[t];
    float4 bv = ((const float4*)beta)[t];
    float o4[4];
    o4[0] = (v.x - mu) * r * gv.x + bv.x;
    o4[1] = (v.y - mu) * r * gv.y + bv.y;
    o4[2] = (v.z - mu) * r * gv.z + bv.z;
    o4[3] = (v.w - mu) * r * gv.w + bv.w;
    size_t base = (size_t)row * D_MODEL + 4 * t;
    #pragma unroll
    for (int i = 0; i < 4; i++) {
        bf16 h = __float2bfloat16(o4[i]);
        oh[base + i] = h;
        ol[base + i] = __float2bfloat16(o4[i] - __bfloat162float(h));
    }
}

// ---------------- mma.sync GEMM: CTA 128x256, 8 warps, warp tile 64x64 (R13) ----------------
#define GA_CH  (128 * 48)
#define GB_CH  (256 * 48)
#define GST    73728
#define GA_HL  12288
#define GB_HL  24576
#define GSMEM  (2 * GST)

template <int MODE>
__global__ void __launch_bounds__(256) mma_gemm_kernel(
    const bf16* __restrict__ Ahi, const bf16* __restrict__ Alo,
    const bf16* __restrict__ Bhi, const bf16* __restrict__ Blo,
    int Kdim,
    const float* __restrict__ b0, const float* __restrict__ b1, const float* __restrict__ b2,
    const float* __restrict__ res,
    float* __restrict__ o32,
    bf16* __restrict__ oh0, bf16* __restrict__ ol0,
    bf16* __restrict__ oh1, bf16* __restrict__ ol1,
    bf16* __restrict__ oh2, bf16* __restrict__ ol2)
{
    extern __shared__ char smem[];
    uint32_t sb = smem_u32(smem);
    int tid = threadIdx.x, wid = tid >> 5, lane = tid & 31;
    int wr = wid >> 2, wc = wid & 3;
    int m0 = blockIdx.y * 128, n0 = blockIdx.x * 256;
    const bf16* Asrc[2] = {Ahi, Alo};
    const bf16* Bsrc[2] = {Bhi, Blo};

    auto load_stage = [&](int c, int s) {
        #pragma unroll
        for (int i = 0; i < 12; i++) {
            int idx = i * 256 + tid;
            uint32_t dst; const bf16* src;
            if (idx < 1024) {
                int mat = idx >> 9, rem = idx & 511;
                int row = rem >> 2, q = rem & 3, kk = q >> 1, half = q & 1;
                src = Asrc[mat] + (size_t)(m0 + row) * Kdim + c * 32 + kk * 16 + half * 8;
                dst = sb + s * GST + mat * GA_HL + kk * GA_CH + row * 48 + half * 16;
            } else {
                int j = idx - 1024;
                int mat = j >> 10, rem = j & 1023;
                int row = rem >> 2, q = rem & 3, kk = q >> 1, half = q & 1;
                src = Bsrc[mat] + (size_t)(n0 + row) * Kdim + c * 32 + kk * 16 + half * 8;
                dst = sb + s * GST + 2 * GA_HL + mat * GB_HL + kk * GB_CH + row * 48 + half * 16;
            }
            cp16(dst, src);
        }
    };

    float acc[4][8][4];
    #pragma unroll
    for (int a = 0; a < 4; a++)
        #pragma unroll
        for (int b = 0; b < 8; b++)
            #pragma unroll
            for (int cc = 0; cc < 4; cc++) acc[a][b][cc] = 0.f;

    load_stage(0, 0);
    CP_COMMIT();

    int arow = lane & 15, ahalf = lane >> 4;
    int brow = (lane & 7) + ((lane >> 4) << 3), bhalf = (lane >> 3) & 1;
    int nc = Kdim >> 5;
    for (int c = 0; c < nc; c++) {
        int s = c & 1;
        if (c + 1 < nc) { load_stage(c + 1, s ^ 1); CP_COMMIT(); CP_WAIT1(); }
        else CP_WAIT0();
        __syncthreads();

        #pragma unroll
        for (int kk = 0; kk < 2; kk++) {
            uint32_t ah[4][4], al[4][4];
            #pragma unroll
            for (int mt = 0; mt < 4; mt++) {
                uint32_t ad = sb + s * GST + kk * GA_CH +
                              (uint32_t)(wr * 64 + mt * 16 + arow) * 48 + ahalf * 16;
                ldsm4(ah[mt], ad);
                ldsm4(al[mt], ad + GA_HL);
            }
            uint32_t bh[4][4], bl[4][4];
            #pragma unroll
            for (int p = 0; p < 4; p++) {
                uint32_t bd = sb + s * GST + 2 * GA_HL + kk * GB_CH +
                              (uint32_t)(wc * 64 + p * 16 + brow) * 48 + bhalf * 16;
                ldsm4(bh[p], bd);
                ldsm4(bl[p], bd + GB_HL);
            }
            #pragma unroll
            for (int mt = 0; mt < 4; mt++)
                #pragma unroll
                for (int nt = 0; nt < 8; nt++) {
                    int p = nt >> 1, i0 = (nt & 1) * 2;
                    mma16816(acc[mt][nt], ah[mt], bh[p][i0], bh[p][i0 + 1]);
                    mma16816(acc[mt][nt], ah[mt], bl[p][i0], bl[p][i0 + 1]);
                    mma16816(acc[mt][nt], al[mt], bh[p][i0], bh[p][i0 + 1]);
                }
        }
        __syncthreads();
    }

    #pragma unroll
    for (int mt = 0; mt < 4; mt++) {
        int r0 = m0 + wr * 64 + mt * 16 + (lane >> 2);
        #pragma unroll
        for (int nt = 0; nt < 8; nt++) {
            int nglob = n0 + wc * 64 + nt * 8 + (lane & 3) * 2;
            if (MODE == 0) {
                int z = nglob >> 9;
                int nn = nglob & 511;
                int h = nn >> 6, dh = nn & 63;
                const float* bias = (z == 0) ? b0 : (z == 1) ? b1 : b2;
                bf16* OH = (z == 0) ? oh0 : (z == 1) ? oh1 : oh2;
                bf16* OL = (z == 0) ? ol0 : (z == 1) ? ol1 : ol2;
                float bv0 = bias[nn], bv1 = bias[nn + 1];
                #pragma unroll
                for (int j = 0; j < 2; j++) {
                    int r = r0 + j * 8;
                    int bb = r >> 11, sidx = r & 2047;
                    size_t dst = ((size_t)((bb * N_HEADS + h) * SEQ + sidx)) * D_HEAD + dh;
                    float v0 = acc[mt][nt][2 * j] + bv0;
                    float v1 = acc[mt][nt][2 * j + 1] + bv1;
                    uint32_t hp, lp;
                    split_pack(v0, v1, hp, lp);
                    *(uint32_t*)(OH + dst) = hp;
                    *(uint32_t*)(OL + dst) = lp;
                }
            } else if (MODE == 1) {
                float bv0 = b0[nglob], bv1 = b0[nglob + 1];
                #pragma unroll
                for (int j = 0; j < 2; j++) {
                    int r = r0 + j * 8;
                    size_t dst = (size_t)r * D_FF + nglob;
                    float v0 = fmaxf(acc[mt][nt][2 * j] + bv0, 0.f);
                    float v1 = fmaxf(acc[mt][nt][2 * j + 1] + bv1, 0.f);
                    uint32_t hp, lp;
                    split_pack(v0, v1, hp, lp);
                    *(uint32_t*)(oh0 + dst) = hp;
                    *(uint32_t*)(ol0 + dst) = lp;
                }
            } else {
                float bv0 = b0[nglob], bv1 = b0[nglob + 1];
                #pragma unroll
                for (int j = 0; j < 2; j++) {
                    int r = r0 + j * 8;
                    size_t dst = (size_t)r * D_MODEL + nglob;
                    float2 rv = *(const float2*)(res + dst);
                    float2 ov;
                    ov.x = acc[mt][nt][2 * j] + bv0 + rv.x;
                    ov.y = acc[mt][nt][2 * j + 1] + bv1 + rv.y;
                    *(float2*)(o32 + dst) = ov;
                }
            }
        }
    }
}

// ---------------- fused sigmoid attention v3: Q-tile 64, KV 32-key stages, 2 CTAs/SM ----------------
// 8 warps = 4 q-groups (16 rows) x 2 key-groups (16 keys/iter).
// smem 72KB -> 2 CTAs/SM (regs capped 128 via launch_bounds(256,2)).
#define A2KCH  (32 * 48)             // 1536: one d16 chunk of K/V (32 rows)
#define A2KMAT (4 * A2KCH)           // 6144: one matrix (Kh/Kl/Vh/Vl)
#define A2KSTG (4 * A2KMAT)          // 24576 per stage
#define A2QOFF (2 * A2KSTG)          // 49152
#define A2QCH  (64 * 48)             // 3072
#define A2QMAT (4 * A2QCH)           // 12288
#define A2SMEM (A2QOFF + 2 * A2QMAT) // 73728
#define ATT_HSCALE 0.022097086912079608f

__global__ void __launch_bounds__(256, 2) attn_kernel(
    const bf16* __restrict__ Qh, const bf16* __restrict__ Ql,
    const bf16* __restrict__ Kh, const bf16* __restrict__ Kl,
    const bf16* __restrict__ Vh, const bf16* __restrict__ Vl,
    float* __restrict__ O)
{
    extern __shared__ char smem[];
    uint32_t sb = smem_u32(smem);
    int tid = threadIdx.x, wid = tid >> 5, lane = tid & 31;
    int wq = wid >> 1, wk = wid & 1;   // 4 q-groups x 2 key-groups
    int bh = blockIdx.y;
    int q0 = blockIdx.x * 64;
    size_t bhbase = (size_t)bh * SEQ * D_HEAD;

    // stage Q (hi+lo, 64 rows): 1024 cp16
    {
        const bf16* qs[2] = {Qh, Ql};
        #pragma unroll
        for (int i = 0; i < 4; i++) {
            int idx = i * 256 + tid;
            int mat = idx >> 9;
            int rem = idx & 511;
            int row = rem >> 3;
            int q = rem & 7, cc = q >> 1, half = q & 1;
            const bf16* src = qs[mat] + bhbase + (size_t)(q0 + row) * D_HEAD + cc * 16 + half * 8;
            uint32_t dst = sb + A2QOFF + mat * A2QMAT + cc * A2QCH + row * 48 + half * 16;
            cp16(dst, src);
        }
    }

    const bf16* kvs[4] = {Kh, Kl, Vh, Vl};
    auto load_kv = [&](int t0, int s) {
        #pragma unroll
        for (int i = 0; i < 4; i++) {
            int idx = i * 256 + tid;
            int mat = idx >> 8;
            int rem = idx & 255;
            int row = rem >> 3;
            int q = rem & 7, cc = q >> 1, half = q & 1;
            const bf16* src = kvs[mat] + bhbase + (size_t)(t0 + row) * D_HEAD + cc * 16 + half * 8;
            uint32_t dst = sb + s * A2KSTG + mat * A2KMAT + cc * A2KCH + row * 48 + half * 16;
            cp16(dst, src);
        }
    };

    load_kv(0, 0);
    CP_COMMIT();

    float oacc[8][4];
    #pragma unroll
    for (int b = 0; b < 8; b++)
        #pragma unroll
        for (int cc = 0; cc < 4; cc++) oacc[b][cc] = 0.f;

    int arow = lane & 15, ahalf = lane >> 4;
    int brow = (lane & 7) + ((lane >> 4) << 3), bhalf = (lane >> 3) & 1;
    const int niter = SEQ / 32;
    for (int c = 0; c < niter; c++) {
        int s = c & 1;
        if (c + 1 < niter) { load_kv((c + 1) * 32, s ^ 1); CP_COMMIT(); CP_WAIT1(); }
        else CP_WAIT0();
        __syncthreads();

        // ---- S = Q @ K^T (warp: 16 q x 16 keys) ----
        float sacc[2][4];
        #pragma unroll
        for (int b = 0; b < 2; b++)
            #pragma unroll
            for (int cc = 0; cc < 4; cc++) sacc[b][cc] = 0.f;

        #pragma unroll
        for (int cc = 0; cc < 4; cc++) {
            uint32_t qah[4], qal[4];
            {
                uint32_t ad = sb + A2QOFF + cc * A2QCH +
                              (uint32_t)(wq * 16 + arow) * 48 + ahalf * 16;
                ldsm4(qah, ad);
                ldsm4(qal, ad + A2QMAT);
            }
            uint32_t kbh[4], kbl[4];
            {
                uint32_t bd = sb + s * A2KSTG + cc * A2KCH +
                              (uint32_t)(wk * 16 + brow) * 48 + bhalf * 16;
                ldsm4(kbh, bd);
                ldsm4(kbl, bd + A2KMAT);
            }
            #pragma unroll
            for (int nt = 0; nt < 2; nt++) {
                mma16816(sacc[nt], qah, kbh[nt * 2], kbh[nt * 2 + 1]);
                mma16816(sacc[nt], qah, kbl[nt * 2], kbl[nt * 2 + 1]);
                mma16816(sacc[nt], qal, kbh[nt * 2], kbh[nt * 2 + 1]);
            }
        }

        // ---- sigmoid + C->A repack in regs ----
        #pragma unroll
        for (int nt = 0; nt < 2; nt++)
            #pragma unroll
            for (int i = 0; i < 4; i++)
                sacc[nt][i] = sigmoid_fast(sacc[nt][i] * ATT_HSCALE);

        // A-frag order: a0=(row,k0-7), a1=(row+8,k0-7), a2=(row,k8-15), a3=(row+8,k8-15)
        uint32_t Sh[4], Sl[4];
        split_pack(sacc[0][0], sacc[0][1], Sh[0], Sl[0]);
        split_pack(sacc[0][2], sacc[0][3], Sh[1], Sl[1]);
        split_pack(sacc[1][0], sacc[1][1], Sh[2], Sl[2]);
        split_pack(sacc[1][2], sacc[1][3], Sh[3], Sl[3]);

        // ---- O += S @ V (warp: 16 q x 64 dims over its 16 keys) ----
        #pragma unroll
        for (int dg = 0; dg < 4; dg++) {
            uint32_t vbh[4], vbl[4];
            uint32_t vad = sb + s * A2KSTG + 2 * A2KMAT + dg * A2KCH +
                           (uint32_t)(wk * 16 + (lane & 15)) * 48 + (lane >> 4) * 16;
            ldsm4t(vbh, vad);
            ldsm4t(vbl, vad + A2KMAT);
            #pragma unroll
            for (int nt2 = 0; nt2 < 2; nt2++) {
                float* o = oacc[dg * 2 + nt2];
                mma16816(o, Sh, vbh[nt2 * 2], vbh[nt2 * 2 + 1]);
                mma16816(o, Sh, vbl[nt2 * 2], vbl[nt2 * 2 + 1]);
                mma16816(o, Sl, vbh[nt2 * 2], vbh[nt2 * 2 + 1]);
            }
        }
        __syncthreads();
    }

    // ---- combine the two key-group partials, write [B,S,D] ----
    if (wk == 1) {
        #pragma unroll
        for (int nt = 0; nt < 8; nt++)
            #pragma unroll
            for (int j = 0; j < 2; j++) {
                int r = (lane >> 2) + j * 8;
                int col = nt * 8 + (lane & 3) * 2;
                float2 p; p.x = oacc[nt][2 * j]; p.y = oacc[nt][2 * j + 1];
                *(float2*)(smem + wq * 4096 + r * 256 + col * 4) = p;
            }
    }
    __syncthreads();
    if (wk == 0) {
        int b = bh >> 3, h = bh & 7;
        #pragma unroll
        for (int nt = 0; nt < 8; nt++)
            #pragma unroll
            for (int j = 0; j < 2; j++) {
                int r = (lane >> 2) + j * 8;
                int col = nt * 8 + (lane & 3) * 2;
                float2 p = *(const float2*)(smem + wq * 4096 + r * 256 + col * 4);
                float2 o;
                o.x = oacc[nt][2 * j] + p.x;
                o.y = oacc[nt][2 * j + 1] + p.y;
                *(float2*)(O + (size_t)(b * SEQ + q0 + wq * 16 + r) * D_MODEL + h * D_HEAD + col) = o;
            }
    }
}

// ---------------- launch ----------------
extern "C" void kernel_launch(void* const* d_in, const int* in_sizes, int n_in,
                              void* d_out, int out_size) {
    const float* x   = (const float*)d_in[0];
    const float* Wq  = (const float*)d_in[1];
    const float* bq  = (const float*)d_in[2];
    const float* Wk  = (const float*)d_in[3];
    const float* bk  = (const float*)d_in[4];
    const float* Wv  = (const float*)d_in[5];
    const float* bv  = (const float*)d_in[6];
    const float* W1  = (const float*)d_in[7];
    const float* b1  = (const float*)d_in[8];
    const float* W2  = (const float*)d_in[9];
    const float* b2  = (const float*)d_in[10];
    const float* g1  = (const float*)d_in[11];
    const float* be1 = (const float*)d_in[12];
    const float* g2  = (const float*)d_in[13];
    const float* be2 = (const float*)d_in[14];
    float* out = (float*)d_out;

    bf16 *p_xh, *p_xl, *p_x2h, *p_x2l, *p_fh, *p_fl;
    bf16 *p_qh, *p_ql, *p_kh, *p_kl, *p_vh, *p_vl;
    bf16 *p_wqh, *p_wql, *p_w1h, *p_w1l, *p_w2h, *p_w2l;
    float *p_attn, *p_x2;
    cudaGetSymbolAddress((void**)&p_xh, g_xh);
    cudaGetSymbolAddress((void**)&p_xl, g_xl);
    cudaGetSymbolAddress((void**)&p_qh, g_qh);
    cudaGetSymbolAddress((void**)&p_ql, g_ql);
    cudaGetSymbolAddress((void**)&p_kh, g_kh);
    cudaGetSymbolAddress((void**)&p_kl, g_kl);
    cudaGetSymbolAddress((void**)&p_vh, g_vh);
    cudaGetSymbolAddress((void**)&p_vl, g_vl);
    cudaGetSymbolAddress((void**)&p_attn, g_attn);
    cudaGetSymbolAddress((void**)&p_x2, g_x2);
    cudaGetSymbolAddress((void**)&p_x2h, g_x2h);
    cudaGetSymbolAddress((void**)&p_x2l, g_x2l);
    cudaGetSymbolAddress((void**)&p_fh, g_fh);
    cudaGetSymbolAddress((void**)&p_fl, g_fl);
    cudaGetSymbolAddress((void**)&p_wqh, g_wqh);
    cudaGetSymbolAddress((void**)&p_wql, g_wql);
    cudaGetSymbolAddress((void**)&p_w1h, g_w1h);
    cudaGetSymbolAddress((void**)&p_w1l, g_w1l);
    cudaGetSymbolAddress((void**)&p_w2h, g_w2h);
    cudaGetSymbolAddress((void**)&p_w2l, g_w2l);

    cudaFuncSetAttribute(mma_gemm_kernel<0>, cudaFuncAttributeMaxDynamicSharedMemorySize, GSMEM);
    cudaFuncSetAttribute(mma_gemm_kernel<1>, cudaFuncAttributeMaxDynamicSharedMemorySize, GSMEM);
    cudaFuncSetAttribute(mma_gemm_kernel<2>, cudaFuncAttributeMaxDynamicSharedMemorySize, GSMEM);
    cudaFuncSetAttribute(attn_kernel, cudaFuncAttributeMaxDynamicSharedMemorySize, A2SMEM);

    // 0. fused weight transpose+split (one launch)
    transpose_split_all_kernel<<<2816, dim3(32, 8)>>>(
        Wq, Wk, Wv, W1, W2, p_wqh, p_wql, p_w1h, p_w1l, p_w2h, p_w2l);
    // 1. LN1 -> bf16 hi/lo
    ln_kernel<<<M_TOTAL, 128>>>(x, g1, be1, p_xh, p_xl);
    // 2. QKV: bf16 hi/lo head-permuted outputs
    mma_gemm_kernel<0><<<dim3(3*D_MODEL/256, M_TOTAL/128), 256, GSMEM>>>(
        p_xh, p_xl, p_wqh, p_wql, D_MODEL, bq, bk, bv, nullptr, nullptr,
        p_qh, p_ql, p_kh, p_kl, p_vh, p_vl);
    // 3. fused sigmoid attention v3 (2 CTAs/SM)
    attn_kernel<<<dim3(SEQ/64, BH), 256, A2SMEM>>>(
        p_qh, p_ql, p_kh, p_kl, p_vh, p_vl, p_attn);
    // 4. residual + LN2
    addln_kernel<<<M_TOTAL, 128>>>(x, p_attn, g2, be2, p_x2, p_x2h, p_x2l);
    // 5. FFN1: relu(xn2 @ W1 + b1) -> bf16 hi/lo
    mma_gemm_kernel<1><<<dim3(D_FF/256, M_TOTAL/128), 256, GSMEM>>>(
        p_x2h, p_x2l, p_w1h, p_w1l, D_MODEL, b1, nullptr, nullptr, nullptr, nullptr,
        p_fh, p_fl, nullptr, nullptr, nullptr, nullptr);
    // 6. FFN2: ffh @ W2 + b2 + x2 -> out
    mma_gemm_kernel<2><<<dim3(D_MODEL/256, M_TOTAL/128), 256, GSMEM>>>(
        p_fh, p_fl, p_w2h, p_w2l, D_FF, b2, nullptr, nullptr, p_x2, out,
        nullptr, nullptr, nullptr, nullptr, nullptr, nullptr);
}